// round 5
// baseline (speedup 1.0000x reference)
#include <cuda_runtime.h>
#include <math.h>

#define SIM_THREADS 1024
#define CHUNK 32768                      // bulk-store chunk (fits in reused buf)

// phys layout: pad 4 float2 slots per 16 -> conflict-free strided stage access
__device__ __forceinline__ int SW_PHYS(int i) { return i + ((i >> 4) << 2); }

__device__ __forceinline__ float2 cmul(float2 a, float2 b) {
    return make_float2(a.x * b.x - a.y * b.y, a.x * b.y + a.y * b.x);
}

// ---- packed f32x2 helpers ----
__device__ __forceinline__ unsigned long long pack2(float x, float y) {
    unsigned long long r;
    asm("mov.b64 %0, {%1, %2};" : "=l"(r) : "f"(x), "f"(y));
    return r;
}
__device__ __forceinline__ float2 unpack2(unsigned long long v) {
    float2 r;
    asm("mov.b64 {%0, %1}, %2;" : "=f"(r.x), "=f"(r.y) : "l"(v));
    return r;
}
__device__ __forceinline__ unsigned long long ffma2(unsigned long long a,
                                                    unsigned long long b,
                                                    unsigned long long c) {
    unsigned long long d;
    asm("fma.rn.f32x2 %0, %1, %2, %3;" : "=l"(d) : "l"(a), "l"(b), "l"(c));
    return d;
}
__device__ __forceinline__ unsigned long long fmul2(unsigned long long a,
                                                    unsigned long long b) {
    unsigned long long d;
    asm("mul.rn.f32x2 %0, %1, %2;" : "=l"(d) : "l"(a), "l"(b));
    return d;
}
__device__ __forceinline__ unsigned smem_u32(const void* p) {
    unsigned a;
    asm("{ .reg .u64 t; cvta.to.shared.u64 t, %1; cvt.u32.u64 %0, t; }"
        : "=r"(a) : "l"(p));
    return a;
}

// 4x4 complex mat-vec in packed form. M4[e*4+e2] = {mx, mx, -my, my}.
__device__ __forceinline__ void mat4_apply(const float4* __restrict__ M4,
                                           const unsigned long long* a,
                                           const unsigned long long* s,
                                           unsigned long long* outv) {
    #pragma unroll
    for (int e = 0; e < 4; e++) {
        float4 q0 = M4[e * 4 + 0];
        float4 q1 = M4[e * 4 + 1];
        float4 q2 = M4[e * 4 + 2];
        float4 q3 = M4[e * 4 + 3];
        const unsigned long long* p0 = reinterpret_cast<const unsigned long long*>(&q0);
        const unsigned long long* p1 = reinterpret_cast<const unsigned long long*>(&q1);
        const unsigned long long* p2 = reinterpret_cast<const unsigned long long*>(&q2);
        const unsigned long long* p3 = reinterpret_cast<const unsigned long long*>(&q3);
        unsigned long long o = fmul2(p0[0], a[0]);
        o = ffma2(p0[1], s[0], o);
        o = ffma2(p1[0], a[1], o);
        o = ffma2(p1[1], s[1], o);
        o = ffma2(p2[0], a[2], o);
        o = ffma2(p2[1], s[2], o);
        o = ffma2(p3[0], a[3], o);
        o = ffma2(p3[1], s[3], o);
        outv[e] = o;
    }
}

// In-place 4x4 stage on bits (B, B+1); thread owns one quad; padded layout.
template<int B>
__device__ __forceinline__ void apply_stage(float2* buf, const float4* M4, int tid) {
    const int m = 1 << B;
    const int stride = (B >= 4) ? (m + (m >> 2)) : m;   // phys stride of quad
    const int low = tid & (m - 1);
    const int base = ((tid >> B) << (B + 2)) | low;
    const int pb = SW_PHYS(base);
    unsigned long long a[4], s[4], o[4];
    #pragma unroll
    for (int k = 0; k < 4; k++) {
        float2 v = buf[pb + k * stride];
        a[k] = pack2(v.x, v.y);
        s[k] = pack2(v.y, v.x);
    }
    mat4_apply(M4, a, s, o);
    #pragma unroll
    for (int k = 0; k < 4; k++)
        buf[pb + k * stride] = unpack2(o[k]);
    __syncthreads();
}

// Fused kernel: every block redundantly computes the circuit + MLP (5 us of
// FMA on its own SM), then bulk-stores its share of the 64 MiB output via TMA.
__global__ __launch_bounds__(SIM_THREADS, 1)
void qae_fused_kernel(const float* __restrict__ w,     // (3,12,3)
                      const float* __restrict__ W1,    // (32,12)
                      const float* __restrict__ b1,    // (32,)
                      const float* __restrict__ W2,    // (16,32)
                      const float* __restrict__ b2,    // (16,)
                      float* __restrict__ out,
                      long long nbytes)
{
    __shared__ __align__(128) float2 buf[5120];   // 40 KB statevector / pattern
    __shared__ float4 sM4[12][16];
    __shared__ float2 sG[36][4];
    __shared__ float2 sHi[64], sLo[64];
    __shared__ int    sBinv[12];
    __shared__ int    smask[12];
    __shared__ float  sPart[32][12];
    __shared__ float  sZ[12], sH[32];
    __shared__ float4 sPix4[4];                   // 16 final pixels

    const int tid = threadIdx.x;

    // ---- per-(layer,qubit) 2x2 gates: M = RZ @ RY @ RX ----
    if (tid < 36) {
        const float* wp = w + tid * 3;
        float hx = 0.5f * wp[0], hy = 0.5f * wp[1], hz = 0.5f * wp[2];
        float cx, sx, cy, sy, cz, sz;
        sincosf(hx, &sx, &cx);
        sincosf(hy, &sy, &cy);
        sincosf(hz, &sz, &cz);
        float2 RX00 = make_float2(cx, 0.f), RX01 = make_float2(0.f, -sx);
        float2 RX10 = make_float2(0.f, -sx), RX11 = make_float2(cx, 0.f);
        float2 RY00 = make_float2(cy, 0.f), RY01 = make_float2(-sy, 0.f);
        float2 RY10 = make_float2(sy, 0.f), RY11 = make_float2(cy, 0.f);
        float2 RZ0 = make_float2(cz, -sz), RZ1 = make_float2(cz, sz);
        float2 t00 = cmul(RY00, RX00), t00b = cmul(RY01, RX10);
        float2 t01 = cmul(RY00, RX01), t01b = cmul(RY01, RX11);
        float2 t10 = cmul(RY10, RX00), t10b = cmul(RY11, RX10);
        float2 t11 = cmul(RY10, RX01), t11b = cmul(RY11, RX11);
        float2 A00 = make_float2(t00.x + t00b.x, t00.y + t00b.y);
        float2 A01 = make_float2(t01.x + t01b.x, t01.y + t01b.y);
        float2 A10 = make_float2(t10.x + t10b.x, t10.y + t10b.y);
        float2 A11 = make_float2(t11.x + t11b.x, t11.y + t11b.y);
        sG[tid][0] = cmul(RZ0, A00);
        sG[tid][1] = cmul(RZ0, A01);
        sG[tid][2] = cmul(RZ1, A10);
        sG[tid][3] = cmul(RZ1, A11);
    }
    // ---- basis of inverse CNOT-ring permutation (GF(2)-linear) ----
    if (tid >= 64 && tid < 76) {
        int b = tid - 64;
        int j = 1 << b;
        #pragma unroll
        for (int q = 11; q >= 0; q--) {
            int c = 11 - q;
            int t = 11 - ((q + 1) % 12);
            if ((j >> c) & 1) j ^= (1 << t);
        }
        sBinv[b] = j;
    }
    // ---- forward-perm parity masks ----
    if (tid == 128) {
        int m[12];
        #pragma unroll
        for (int k = 0; k < 12; k++) m[k] = 1 << k;
        #pragma unroll
        for (int q = 0; q < 12; q++) {
            int c = 11 - q;
            int t = 11 - ((q + 1) % 12);
            m[t] ^= m[c];
        }
        #pragma unroll
        for (int k = 0; k < 12; k++) smask[k] = m[k];
    }
    __syncthreads();

    // ---- register-resident gather indices g(4t+k) via linearity ----
    int gr[4];
    {
        int idx4 = tid << 2;
        int gb = 0;
        #pragma unroll
        for (int b = 2; b < 12; b++)
            if ((idx4 >> b) & 1) gb ^= sBinv[b];
        gr[0] = gb;
        gr[1] = gb ^ sBinv[0];
        gr[2] = gb ^ sBinv[1];
        gr[3] = gb ^ sBinv[1] ^ sBinv[0];
    }

    // ---- packed 4x4 stage matrices for layers 2,3 ----
    if (tid < 192) {
        int s = tid >> 4, e = tid & 15;
        int l = 1 + s / 6, b = s % 6;
        int qlo = 11 - 2 * b, qhi = 10 - 2 * b;
        int eo = e >> 2, ei = e & 3;
        float2 mh = sG[l * 12 + qhi][(eo >> 1) * 2 + (ei >> 1)];
        float2 ml = sG[l * 12 + qlo][(eo & 1) * 2 + (ei & 1)];
        float2 mm = cmul(mh, ml);
        sM4[s][e] = make_float4(mm.x, mm.x, -mm.y, mm.y);
    }
    // ---- layer-1 product-state prefix tables ----
    if (tid >= 256 && tid < 320) {        // hi: qubits 0..5 <-> bits 11..6
        int h = tid - 256;
        float2 p = make_float2(1.f, 0.f);
        #pragma unroll
        for (int q = 0; q < 6; q++) {
            int bit = (h >> (5 - q)) & 1;
            p = cmul(p, bit ? sG[q][2] : sG[q][0]);
        }
        sHi[h] = p;
    } else if (tid >= 320 && tid < 384) { // lo: qubits 6..11 <-> bits 5..0
        int mI = tid - 320;
        float2 p = make_float2(1.f, 0.f);
        #pragma unroll
        for (int q = 6; q < 12; q++) {
            int bit = (mI >> (11 - q)) & 1;
            p = cmul(p, bit ? sG[q][2] : sG[q][0]);
        }
        sLo[mI] = p;
    }
    __syncthreads();

    // ===== layer 2, stage (0,1) with P1-folded product gather =====
    {
        const int pb = SW_PHYS(tid << 2);
        unsigned long long a[4], s[4], o[4];
        #pragma unroll
        for (int k = 0; k < 4; k++) {
            float2 v = cmul(sHi[gr[k] >> 6], sLo[gr[k] & 63]);
            a[k] = pack2(v.x, v.y);
            s[k] = pack2(v.y, v.x);
        }
        mat4_apply(sM4[0], a, s, o);
        #pragma unroll
        for (int e = 0; e < 4; e++) buf[pb + e] = unpack2(o[e]);
        __syncthreads();
    }
    apply_stage<2>(buf,  sM4[1], tid);
    apply_stage<4>(buf,  sM4[2], tid);
    apply_stage<6>(buf,  sM4[3], tid);
    apply_stage<8>(buf,  sM4[4], tid);
    apply_stage<10>(buf, sM4[5], tid);

    // ===== layer 3, stage (0,1) with P2-folded gather =====
    {
        const int pb = SW_PHYS(tid << 2);
        unsigned long long a[4], s[4], o[4];
        #pragma unroll
        for (int k = 0; k < 4; k++) {
            float2 v = buf[SW_PHYS(gr[k])];
            a[k] = pack2(v.x, v.y);
            s[k] = pack2(v.y, v.x);
        }
        __syncthreads();                  // all reads done before overwrites
        mat4_apply(sM4[6], a, s, o);
        #pragma unroll
        for (int e = 0; e < 4; e++) buf[pb + e] = unpack2(o[e]);
        __syncthreads();
    }
    apply_stage<2>(buf,  sM4[7], tid);
    apply_stage<4>(buf,  sM4[8], tid);
    apply_stage<6>(buf,  sM4[9], tid);
    apply_stage<8>(buf,  sM4[10], tid);
    apply_stage<10>(buf, sM4[11], tid);

    // ===== <Z_q> reduction, P3 folded as parity sign masks =====
    float zloc[12];
    #pragma unroll
    for (int q = 0; q < 12; q++) zloc[q] = 0.f;
    {
        const int pb = SW_PHYS(tid << 2);
        #pragma unroll
        for (int k = 0; k < 4; k++) {
            int i = (tid << 2) + k;
            float2 aa = buf[pb + k];
            float pr = aa.x * aa.x + aa.y * aa.y;
            #pragma unroll
            for (int q = 0; q < 12; q++)
                zloc[q] += (__popc(i & smask[11 - q]) & 1) ? -pr : pr;
        }
    }
    #pragma unroll
    for (int q = 0; q < 12; q++) {
        float x = zloc[q];
        #pragma unroll
        for (int off = 16; off > 0; off >>= 1)
            x += __shfl_down_sync(0xFFFFFFFFu, x, off);
        zloc[q] = x;
    }
    int warp = tid >> 5, lane = tid & 31;
    if (lane == 0) {
        #pragma unroll
        for (int q = 0; q < 12; q++) sPart[warp][q] = zloc[q];
    }
    __syncthreads();
    if (tid < 12) {
        float s = 0.f;
        #pragma unroll
        for (int wi = 0; wi < 32; wi++) s += sPart[wi][tid];
        sZ[tid] = s;
    }
    __syncthreads();

    // ---- MLP head: 12 -> 32 (ReLU) -> 16 (sigmoid) ----
    if (tid < 32) {
        float acc = b1[tid];
        #pragma unroll
        for (int k = 0; k < 12; k++) acc += W1[tid * 12 + k] * sZ[k];
        sH[tid] = fmaxf(acc, 0.f);
    }
    __syncthreads();
    if (tid < 16) {
        float acc = b2[tid];
        #pragma unroll
        for (int k = 0; k < 32; k++) acc += W2[tid * 32 + k] * sH[k];
        reinterpret_cast<float*>(sPix4)[tid] = 1.f / (1.f + expf(-acc));
    }
    __syncthreads();

    // ===== broadcast: reuse buf as 32 KB replicated pattern, TMA bulk store ==
    float4* pat = reinterpret_cast<float4*>(buf);
    {
        float4 v = sPix4[tid & 3];
        pat[tid]        = v;       // 1024 % 4 == 0 -> same (slot & 3) phase
        pat[tid + 1024] = v;       // 2048 float4 = 32 KB
    }
    __syncthreads();

    const long long nchunks = nbytes / CHUNK;
    if (tid == 0) {
        asm volatile("fence.proxy.async.shared::cta;" ::: "memory");
        const unsigned saddr = smem_u32(pat);
        unsigned long long gbase = (unsigned long long)out;
        for (long long c = blockIdx.x; c < nchunks; c += gridDim.x) {
            unsigned long long gaddr = gbase + (unsigned long long)c * CHUNK;
            asm volatile(
                "cp.async.bulk.global.shared::cta.bulk_group [%0], [%1], %2;"
                :: "l"(gaddr), "r"(saddr), "r"((unsigned)CHUNK) : "memory");
        }
        asm volatile("cp.async.bulk.commit_group;" ::: "memory");
        asm volatile("cp.async.bulk.wait_group 0;" ::: "memory");
    }

    // ---- tail (nbytes not multiple of CHUNK): plain vector stores, block 0 --
    long long done = nchunks * CHUNK;
    if (blockIdx.x == 0 && done < nbytes) {
        long long n4t = (nbytes - done) >> 4;
        float4* o = reinterpret_cast<float4*>((char*)out + done);
        for (long long k = tid; k < n4t; k += SIM_THREADS)
            o[k] = sPix4[(int)(k & 3)];
    }
}

extern "C" void kernel_launch(void* const* d_in, const int* in_sizes, int n_in,
                              void* d_out, int out_size)
{
    // metadata order: images, qweights, W1, b1, W2, b2
    const float* w  = (const float*)d_in[1];
    const float* W1 = (const float*)d_in[2];
    const float* b1 = (const float*)d_in[3];
    const float* W2 = (const float*)d_in[4];
    const float* b2 = (const float*)d_in[5];

    long long nbytes = (long long)out_size * 4;      // float output
    qae_fused_kernel<<<128, SIM_THREADS>>>(w, W1, b1, W2, b2,
                                           (float*)d_out, nbytes);
}

// round 6
// speedup vs baseline: 1.4046x; 1.4046x over previous
#include <cuda_runtime.h>
#include <math.h>

typedef unsigned long long u64;

__device__ float g_pix[16];   // 16 sigmoid pixels (final pattern)

// padded phys layout: one 8B slot per 16 amps -> conflict-free in all 3 rounds
__device__ __forceinline__ int PHYS(int i) { return i + (i >> 4); }

__device__ __forceinline__ float2 cmul(float2 a, float2 b) {
    return make_float2(a.x * b.x - a.y * b.y, a.x * b.y + a.y * b.x);
}
__device__ __forceinline__ u64 pack2(float x, float y) {
    u64 r; asm("mov.b64 %0, {%1, %2};" : "=l"(r) : "f"(x), "f"(y)); return r;
}
__device__ __forceinline__ float2 unpack2(u64 v) {
    float2 r; asm("mov.b64 {%0, %1}, %2;" : "=f"(r.x), "=f"(r.y) : "l"(v)); return r;
}
__device__ __forceinline__ u64 swp(u64 v) {
    float2 t = unpack2(v); return pack2(t.y, t.x);
}
__device__ __forceinline__ u64 ffma2(u64 a, u64 b, u64 c) {
    u64 d; asm("fma.rn.f32x2 %0, %1, %2, %3;" : "=l"(d) : "l"(a), "l"(b), "l"(c)); return d;
}
__device__ __forceinline__ u64 fmul2(u64 a, u64 b) {
    u64 d; asm("mul.rn.f32x2 %0, %1, %2;" : "=l"(d) : "l"(a), "l"(b)); return d;
}

// Apply two 4x4 complex stages to 16 register amps.
// Stage A groups quads {A[4c+j]} (bits f0,f1); stage B groups {A[4j+c]} (bits f2,f3).
// Msh entries are {mx, mx, -my, my}.
__device__ __forceinline__ void stage_pair(const float4* __restrict__ MshA,
                                           const float4* __restrict__ MshB,
                                           u64* A) {
    {   // stage A
        u64 mr[16], mi[16];
        #pragma unroll
        for (int e = 0; e < 16; e++) {
            float4 q = MshA[e];
            mr[e] = pack2(q.x, q.y);
            mi[e] = pack2(q.z, q.w);
        }
        #pragma unroll
        for (int c = 0; c < 4; c++) {
            u64 x0 = A[4*c], x1 = A[4*c+1], x2 = A[4*c+2], x3 = A[4*c+3];
            u64 s0 = swp(x0), s1 = swp(x1), s2 = swp(x2), s3 = swp(x3);
            #pragma unroll
            for (int e = 0; e < 4; e++) {
                u64 o = fmul2(mr[e*4+0], x0);
                o = ffma2(mi[e*4+0], s0, o);
                o = ffma2(mr[e*4+1], x1, o); o = ffma2(mi[e*4+1], s1, o);
                o = ffma2(mr[e*4+2], x2, o); o = ffma2(mi[e*4+2], s2, o);
                o = ffma2(mr[e*4+3], x3, o); o = ffma2(mi[e*4+3], s3, o);
                A[4*c+e] = o;
            }
        }
    }
    {   // stage B
        u64 mr[16], mi[16];
        #pragma unroll
        for (int e = 0; e < 16; e++) {
            float4 q = MshB[e];
            mr[e] = pack2(q.x, q.y);
            mi[e] = pack2(q.z, q.w);
        }
        #pragma unroll
        for (int c = 0; c < 4; c++) {
            u64 x0 = A[c], x1 = A[4+c], x2 = A[8+c], x3 = A[12+c];
            u64 s0 = swp(x0), s1 = swp(x1), s2 = swp(x2), s3 = swp(x3);
            #pragma unroll
            for (int e = 0; e < 4; e++) {
                u64 o = fmul2(mr[e*4+0], x0);
                o = ffma2(mi[e*4+0], s0, o);
                o = ffma2(mr[e*4+1], x1, o); o = ffma2(mi[e*4+1], s1, o);
                o = ffma2(mr[e*4+2], x2, o); o = ffma2(mi[e*4+2], s2, o);
                o = ffma2(mr[e*4+3], x3, o); o = ffma2(mi[e*4+3], s3, o);
                A[4*e+c] = o;
            }
        }
    }
}

__global__ __launch_bounds__(256, 1)
void qae_sim_kernel(const float* __restrict__ w,     // (3,12,3)
                    const float* __restrict__ W1,    // (32,12)
                    const float* __restrict__ b1,    // (32,)
                    const float* __restrict__ W2,    // (16,32)
                    const float* __restrict__ b2)    // (16,)
{
    __shared__ u64    buf[4352];          // 4096 amps padded (34 KB)
    __shared__ float4 sM4[12][16];        // packed {mx,mx,-my,my} stage mats
    __shared__ float2 sG[36][4];          // per (layer,qubit) fused gate
    __shared__ float2 sHi[64], sLo[64];   // layer-1 product prefix tables
    __shared__ int    sBinv[12];          // basis of inverse CNOT-ring perm
    __shared__ int    smask[12];          // forward-perm parity masks
    __shared__ float  sPart[8][12];
    __shared__ float  sZ[12], sH[32];

    const int t = threadIdx.x;            // 0..255

    // ---- per-(layer,qubit) 2x2 gates ----
    if (t < 36) {
        const float* wp = w + t * 3;
        int layer = t / 12;
        float hx = 0.5f * wp[0], hy = 0.5f * wp[1], hz = 0.5f * wp[2];
        float cx, sx, cy, sy, cz, sz;
        __sincosf(hx, &sx, &cx);
        __sincosf(hy, &sy, &cy);
        __sincosf(hz, &sz, &cz);
        float2 RX00 = make_float2(cx, 0.f), RX01 = make_float2(0.f, -sx);
        float2 RX10 = make_float2(0.f, -sx), RX11 = make_float2(cx, 0.f);
        float2 RY00 = make_float2(cy, 0.f), RY01 = make_float2(-sy, 0.f);
        float2 RY10 = make_float2(sy, 0.f), RY11 = make_float2(cy, 0.f);
        float2 t00 = cmul(RY00, RX00), t00b = cmul(RY01, RX10);
        float2 t01 = cmul(RY00, RX01), t01b = cmul(RY01, RX11);
        float2 t10 = cmul(RY10, RX00), t10b = cmul(RY11, RX10);
        float2 t11 = cmul(RY10, RX01), t11b = cmul(RY11, RX11);
        float2 A00 = make_float2(t00.x + t00b.x, t00.y + t00b.y);
        float2 A01 = make_float2(t01.x + t01b.x, t01.y + t01b.y);
        float2 A10 = make_float2(t10.x + t10b.x, t10.y + t10b.y);
        float2 A11 = make_float2(t11.x + t11b.x, t11.y + t11b.y);
        if (layer == 2) {
            // final layer: RZ is diagonal phases -> probabilities unchanged; drop it
            sG[t][0] = A00; sG[t][1] = A01; sG[t][2] = A10; sG[t][3] = A11;
        } else {
            float2 RZ0 = make_float2(cz, -sz), RZ1 = make_float2(cz, sz);
            sG[t][0] = cmul(RZ0, A00);
            sG[t][1] = cmul(RZ0, A01);
            sG[t][2] = cmul(RZ1, A10);
            sG[t][3] = cmul(RZ1, A11);
        }
    }
    // ---- basis of inverse CNOT-ring permutation (GF(2)-linear) ----
    if (t >= 64 && t < 76) {
        int b = t - 64;
        int j = 1 << b;
        #pragma unroll
        for (int q = 11; q >= 0; q--) {
            int c = 11 - q;
            int tt = 11 - ((q + 1) % 12);
            if ((j >> c) & 1) j ^= (1 << tt);
        }
        sBinv[b] = j;
    }
    // ---- forward-perm parity masks ----
    if (t == 128) {
        int m[12];
        #pragma unroll
        for (int k = 0; k < 12; k++) m[k] = 1 << k;
        #pragma unroll
        for (int q = 0; q < 12; q++) {
            int c = 11 - q;
            int tt = 11 - ((q + 1) % 12);
            m[tt] ^= m[c];
        }
        #pragma unroll
        for (int k = 0; k < 12; k++) smask[k] = m[k];
    }
    __syncthreads();

    // ---- packed 4x4 stage matrices (layers 2,3) ----
    if (t < 192) {
        int s = t >> 4, e = t & 15;
        int l = 1 + s / 6, b = s % 6;
        int qlo = 11 - 2 * b, qhi = 10 - 2 * b;
        int eo = e >> 2, ei = e & 3;
        float2 mh = sG[l * 12 + qhi][(eo >> 1) * 2 + (ei >> 1)];
        float2 ml = sG[l * 12 + qlo][(eo & 1) * 2 + (ei & 1)];
        float2 mm = cmul(mh, ml);
        sM4[s][e] = make_float4(mm.x, mm.x, -mm.y, mm.y);
    }
    // ---- layer-1 product-state prefix tables ----
    if (t < 64) {                         // hi: qubits 0..5 <-> bits 11..6
        float2 p = make_float2(1.f, 0.f);
        #pragma unroll
        for (int q = 0; q < 6; q++) {
            int bit = (t >> (5 - q)) & 1;
            p = cmul(p, bit ? sG[q][2] : sG[q][0]);
        }
        sHi[t] = p;
    } else if (t < 128) {                 // lo: qubits 6..11 <-> bits 5..0
        int mI = t - 64;
        float2 p = make_float2(1.f, 0.f);
        #pragma unroll
        for (int q = 6; q < 12; q++) {
            int bit = (mI >> (11 - q)) & 1;
            p = cmul(p, bit ? sG[q][2] : sG[q][0]);
        }
        sLo[mI] = p;
    }
    __syncthreads();

    // gather-base for P^-1 over this thread's high bits (bits 4..11 = t)
    int gb = 0;
    #pragma unroll
    for (int b = 0; b < 8; b++)
        if ((t >> b) & 1) gb ^= sBinv[4 + b];
    const int B0 = sBinv[0], B1 = sBinv[1], B2 = sBinv[2], B3 = sBinv[3];

    u64 A[16];

    // ===== layer 2, round 0 (bits 0-3): P1-folded product gather =====
    #pragma unroll
    for (int k = 0; k < 16; k++) {
        int g = gb;
        if (k & 1) g ^= B0;
        if (k & 2) g ^= B1;
        if (k & 4) g ^= B2;
        if (k & 8) g ^= B3;
        float2 v = cmul(sHi[g >> 6], sLo[g & 63]);
        A[k] = pack2(v.x, v.y);
    }
    stage_pair(sM4[0], sM4[1], A);
    #pragma unroll
    for (int k = 0; k < 16; k++) buf[PHYS((t << 4) | k)] = A[k];
    __syncthreads();

    // ===== layer 2, round 1 (bits 4-7) =====
    {
        const int hi = t >> 4, lo = t & 15;
        #pragma unroll
        for (int k = 0; k < 16; k++) A[k] = buf[PHYS((hi << 8) | (k << 4) | lo)];
        stage_pair(sM4[2], sM4[3], A);
        #pragma unroll
        for (int k = 0; k < 16; k++) buf[PHYS((hi << 8) | (k << 4) | lo)] = A[k];
    }
    __syncthreads();

    // ===== layer 2, round 2 (bits 8-11) =====
    #pragma unroll
    for (int k = 0; k < 16; k++) A[k] = buf[PHYS((k << 8) | t)];
    stage_pair(sM4[4], sM4[5], A);
    #pragma unroll
    for (int k = 0; k < 16; k++) buf[PHYS((k << 8) | t)] = A[k];
    __syncthreads();

    // ===== layer 3, round 0 (bits 0-3): P2-folded gather =====
    #pragma unroll
    for (int k = 0; k < 16; k++) {
        int g = gb;
        if (k & 1) g ^= B0;
        if (k & 2) g ^= B1;
        if (k & 4) g ^= B2;
        if (k & 8) g ^= B3;
        A[k] = buf[PHYS(g)];
    }
    __syncthreads();                      // all permuted reads before overwrite
    stage_pair(sM4[6], sM4[7], A);
    #pragma unroll
    for (int k = 0; k < 16; k++) buf[PHYS((t << 4) | k)] = A[k];
    __syncthreads();

    // ===== layer 3, round 1 (bits 4-7) =====
    {
        const int hi = t >> 4, lo = t & 15;
        #pragma unroll
        for (int k = 0; k < 16; k++) A[k] = buf[PHYS((hi << 8) | (k << 4) | lo)];
        stage_pair(sM4[8], sM4[9], A);
        #pragma unroll
        for (int k = 0; k < 16; k++) buf[PHYS((hi << 8) | (k << 4) | lo)] = A[k];
    }
    __syncthreads();

    // ===== layer 3, round 2 (bits 8-11): reduce from registers =====
    #pragma unroll
    for (int k = 0; k < 16; k++) A[k] = buf[PHYS((k << 8) | t)];
    __syncthreads();                      // buf reads done (buf reused for WHT)
    stage_pair(sM4[10], sM4[11], A);

    // per-thread probabilities + 4-bit Walsh-Hadamard over k
    float pr[16];
    #pragma unroll
    for (int k = 0; k < 16; k++) {
        float2 v = unpack2(A[k]);
        pr[k] = fmaf(v.x, v.x, v.y * v.y);
    }
    #pragma unroll
    for (int s = 1; s < 16; s <<= 1) {
        #pragma unroll
        for (int k = 0; k < 16; k++) {
            if (!(k & s)) {
                float u = pr[k], vv = pr[k | s];
                pr[k] = u + vv;
                pr[k | s] = u - vv;
            }
        }
    }
    // spill W to private padded smem slice (dynamic index needs memory)
    float* Wb = reinterpret_cast<float*>(buf) + t * 17;
    #pragma unroll
    for (int h = 0; h < 16; h++) Wb[h] = pr[h];

    // zloc[q] = sign(t) * W[mask_hi]; sign from low 8 bits of mask
    float zloc[12];
    #pragma unroll
    for (int q = 0; q < 12; q++) {
        int m = smask[11 - q];
        float wv = Wb[(m >> 8) & 15];
        zloc[q] = (__popc(t & m & 0xFF) & 1) ? -wv : wv;
    }
    #pragma unroll
    for (int q = 0; q < 12; q++) {
        float x = zloc[q];
        #pragma unroll
        for (int off = 16; off > 0; off >>= 1)
            x += __shfl_down_sync(0xFFFFFFFFu, x, off);
        zloc[q] = x;
    }
    int warp = t >> 5, lane = t & 31;
    if (lane == 0) {
        #pragma unroll
        for (int q = 0; q < 12; q++) sPart[warp][q] = zloc[q];
    }
    __syncthreads();
    if (t < 12) {
        float s = 0.f;
        #pragma unroll
        for (int wi = 0; wi < 8; wi++) s += sPart[wi][t];
        sZ[t] = s;
    }
    __syncthreads();

    // ---- MLP head: 12 -> 32 (ReLU) -> 16 (sigmoid) ----
    if (t < 32) {
        float acc = b1[t];
        #pragma unroll
        for (int k = 0; k < 12; k++) acc += W1[t * 12 + k] * sZ[k];
        sH[t] = fmaxf(acc, 0.f);
    }
    __syncthreads();
    if (t < 16) {
        float acc = b2[t];
        #pragma unroll
        for (int k = 0; k < 32; k++) acc += W2[t * 32 + k] * sH[k];
        g_pix[t] = 1.f / (1.f + __expf(-acc));
    }
}

// Broadcast 64B pattern across the 64 MiB output: 8 unrolled STG.128/thread.
__global__ __launch_bounds__(256)
void qae_bcast_kernel(float4* __restrict__ out, int n4)
{
    int t = blockIdx.x * 256 + threadIdx.x;
    int total = gridDim.x * 256;                    // multiple of 4
    float4 v = reinterpret_cast<const float4*>(g_pix)[t & 3];
    int i = t;
    if (t + 7 * total < n4) {
        #pragma unroll
        for (int k = 0; k < 8; k++) out[t + k * total] = v;
        i = t + 8 * total;
    }
    for (; i < n4; i += total) out[i] = v;
}

extern "C" void kernel_launch(void* const* d_in, const int* in_sizes, int n_in,
                              void* d_out, int out_size)
{
    // metadata order: images, qweights, W1, b1, W2, b2
    const float* w  = (const float*)d_in[1];
    const float* W1 = (const float*)d_in[2];
    const float* b1 = (const float*)d_in[3];
    const float* W2 = (const float*)d_in[4];
    const float* b2 = (const float*)d_in[5];

    qae_sim_kernel<<<1, 256>>>(w, W1, b1, W2, b2);

    int n4 = out_size / 4;                           // float4 count
    int blocks = n4 / (256 * 8);                     // exact for B=1M
    if (blocks < 1) blocks = 1;
    qae_bcast_kernel<<<blocks, 256>>>((float4*)d_out, n4);
}